// round 10
// baseline (speedup 1.0000x reference)
#include <cuda_runtime.h>
#include <cstdint>

#define N_NODES 50000
#define N_EDGES 400000
#define N_PATHS 512
#define DIM 64

// ---------------- device scratch (static: no runtime allocation) ----------------
__device__ float g_deg[N_NODES];
__device__ float g_agg0[N_NODES * DIM];
__device__ float g_agg1[N_NODES * DIM];
__device__ float g_h0[N_NODES * DIM];
__device__ float g_h1[N_NODES * DIM];
__device__ float g_path[N_PATHS * DIM];
__device__ int   g_is32;

// ---------------- common helpers ----------------
__device__ __forceinline__ unsigned f2tf32(float f) {
    unsigned u;
    asm("cvt.rna.tf32.f32 %0, %1;" : "=r"(u) : "f"(f));
    return u;
}

__device__ __forceinline__ unsigned pkhalf2(float lo, float hi) {
    unsigned d;
    asm("cvt.rn.f16x2.f32 %0, %1, %2;" : "=r"(d) : "f"(hi), "f"(lo));
    return d;
}

__device__ __forceinline__ void mma8(float* c, const unsigned* a, unsigned b0, unsigned b1) {
    asm volatile(
        "mma.sync.aligned.m16n8k8.row.col.f32.tf32.tf32.f32 "
        "{%0,%1,%2,%3}, {%4,%5,%6,%7}, {%8,%9}, {%0,%1,%2,%3};"
        : "+f"(c[0]), "+f"(c[1]), "+f"(c[2]), "+f"(c[3])
        : "r"(a[0]), "r"(a[1]), "r"(a[2]), "r"(a[3]), "r"(b0), "r"(b1));
}

__device__ __forceinline__ void mma16h(float* c, unsigned a0, unsigned a1,
                                       unsigned a2, unsigned a3,
                                       unsigned b0, unsigned b1) {
    asm volatile(
        "mma.sync.aligned.m16n8k16.row.col.f32.f16.f16.f32 "
        "{%0,%1,%2,%3}, {%4,%5,%6,%7}, {%8,%9}, {%0,%1,%2,%3};"
        : "+f"(c[0]), "+f"(c[1]), "+f"(c[2]), "+f"(c[3])
        : "r"(a0), "r"(a1), "r"(a2), "r"(a3), "r"(b0), "r"(b1));
}

__device__ __forceinline__ void load_edge(const void* ei, int flag, int e,
                                          int& s, int& d) {
    if (flag) {
        const int* p = (const int*)ei;
        s = __ldg(&p[e]);
        d = __ldg(&p[N_EDGES + e]);
    } else {
        const long long* p = (const long long*)ei;
        s = (int)__ldg(&p[e]);
        d = (int)__ldg(&p[N_EDGES + e]);
    }
}

// ---------------- launch 1: fused init + dtype probe ----------------
__global__ void init_kernel(float* __restrict__ deg, float* __restrict__ agg0,
                            float* __restrict__ agg1, float* __restrict__ pemb,
                            int* __restrict__ flag, const int* __restrict__ ei_w) {
    int i = blockIdx.x * blockDim.x + threadIdx.x;
    if (i < N_NODES) deg[i] = 0.0f;
    if (i < N_NODES * DIM) { agg0[i] = 0.0f; agg1[i] = 0.0f; }
    if (i < N_PATHS * DIM) pemb[i] = 0.0f;
    if (blockIdx.x == 0) {
        int t = threadIdx.x;
        int nz = 0;
#pragma unroll
        for (int k = 0; k < 16; k++) {
            int idx = t * 16 + k;
            if (ei_w[2 * idx + 1] != 0) nz = 1;
        }
        int any = __syncthreads_or(nz);
        if (t == 0) *flag = any;
    }
}

// ---------------- scatter-sum ----------------
template <bool WITH_DEG>
__global__ void scatter_kernel(const float* __restrict__ x,
                               const void* __restrict__ ei,
                               const int* __restrict__ flagp,
                               float* __restrict__ agg,
                               float* __restrict__ deg) {
    int idx = blockIdx.x * blockDim.x + threadIdx.x;
    if (idx >= N_EDGES * 16) return;
    int e = idx >> 4;
    int j = idx & 15;
    int flag = *flagp;
    int s, d;
    load_edge(ei, flag, e, s, d);
    if (WITH_DEG && j == 0) atomicAdd(&deg[d], 1.0f);
    float4 v = __ldg((const float4*)x + (size_t)s * 16 + j);
    atomicAdd((float4*)agg + (size_t)d * 16 + j, v);
}

// ---------------- SAGE layer via tf32 mma ----------------
#define SAGE_AX_STRIDE 132
#define SAGE_W_STRIDE 72
#define SAGE_SMEM_BYTES ((128 * SAGE_AX_STRIDE + 128 * SAGE_W_STRIDE) * 4)

__global__ void __launch_bounds__(256) sage_mma_kernel(
    const float* __restrict__ agg, const float* __restrict__ deg,
    const float* __restrict__ x, const float* __restrict__ Wl,
    const float* __restrict__ Wr, const float* __restrict__ bl,
    float* __restrict__ h) {
    extern __shared__ float sm[];
    float* sAX = sm;
    float* sW  = sm + 128 * SAGE_AX_STRIDE;

    int tid = threadIdx.x;
    int lane = tid & 31;
    int warp = tid >> 5;

    for (int i = tid; i < 1024; i += 256) {
        int k = i >> 4, c4 = i & 15;
        float4 wl = ((const float4*)Wl)[i];
        float4 wr = ((const float4*)Wr)[i];
        *(float4*)&sW[k * SAGE_W_STRIDE + c4 * 4] = wl;
        *(float4*)&sW[(k + 64) * SAGE_W_STRIDE + c4 * 4] = wr;
    }

    int bc = (lane & 3) * 2;
    float bias0[8], bias1[8];
#pragma unroll
    for (int ni = 0; ni < 8; ni++) {
        bias0[ni] = __ldg(&bl[ni * 8 + bc]);
        bias1[ni] = __ldg(&bl[ni * 8 + bc + 1]);
    }

    int ntiles = (N_NODES + 127) / 128;
    for (int t = blockIdx.x; t < ntiles; t += gridDim.x) {
        int base = t * 128;
        __syncthreads();
        for (int i = tid; i < 2048; i += 256) {
            int r = i >> 4, c4 = i & 15;
            int row = base + r;
            float4 va = make_float4(0.f, 0.f, 0.f, 0.f);
            float4 vx = va;
            if (row < N_NODES) {
                va = ((const float4*)agg)[(size_t)row * 16 + c4];
                float iv = 1.0f / fmaxf(deg[row], 1.0f);
                va.x *= iv; va.y *= iv; va.z *= iv; va.w *= iv;
                vx = ((const float4*)x)[(size_t)row * 16 + c4];
            }
            *(float4*)&sAX[r * SAGE_AX_STRIDE + c4 * 4] = va;
            *(float4*)&sAX[r * SAGE_AX_STRIDE + 64 + c4 * 4] = vx;
        }
        __syncthreads();

        float acc[8][4];
#pragma unroll
        for (int ni = 0; ni < 8; ni++) {
            acc[ni][0] = bias0[ni];
            acc[ni][1] = bias1[ni];
            acc[ni][2] = bias0[ni];
            acc[ni][3] = bias1[ni];
        }

        int rb = warp * 16 + (lane >> 2);
        int nb = lane >> 2;
#pragma unroll
        for (int kk = 0; kk < 128; kk += 8) {
            int kA = kk + (lane & 3);
            unsigned a[4];
            a[0] = f2tf32(sAX[rb * SAGE_AX_STRIDE + kA]);
            a[1] = f2tf32(sAX[(rb + 8) * SAGE_AX_STRIDE + kA]);
            a[2] = f2tf32(sAX[rb * SAGE_AX_STRIDE + kA + 4]);
            a[3] = f2tf32(sAX[(rb + 8) * SAGE_AX_STRIDE + kA + 4]);
#pragma unroll
            for (int ni = 0; ni < 8; ni++) {
                unsigned b0 = f2tf32(sW[kA * SAGE_W_STRIDE + ni * 8 + nb]);
                unsigned b1 = f2tf32(sW[(kA + 4) * SAGE_W_STRIDE + ni * 8 + nb]);
                mma8(acc[ni], a, b0, b1);
            }
        }

        int r0 = base + rb;
#pragma unroll
        for (int ni = 0; ni < 8; ni++) {
            int col = ni * 8 + bc;
            if (r0 < N_NODES) {
                float2 o = make_float2(fmaxf(acc[ni][0], 0.f), fmaxf(acc[ni][1], 0.f));
                *(float2*)&h[(size_t)r0 * 64 + col] = o;
            }
            if (r0 + 8 < N_NODES) {
                float2 o = make_float2(fmaxf(acc[ni][2], 0.f), fmaxf(acc[ni][3], 0.f));
                *(float2*)&h[(size_t)(r0 + 8) * 64 + col] = o;
            }
        }
    }
}

// ---------------- big GEMM: warp-specialized hybrid ----------------
// 8 mma warps: fp16 m16n8k16, cols 0..39, 64 rows each.
// 8 fma warps: fma.rn.f32x2, cols 40..63, 64 rows each (2 rows/lane, fp32 exact).
#define A_BUF_BYTES 65536
#define SB_HSTRIDE 40                         // halves per n-row (fp16 tile, cols 0..39)
#define B16_BYTES (40 * SB_HSTRIDE * 2)       // 3200
#define B32_STR 28                            // floats per k-row (24 data + 4 pad, 112B)
#define B32_BYTES (32 * B32_STR * 4)          // 3584
#define OFF_B16_0 (2 * A_BUF_BYTES)
#define OFF_B16_1 (OFF_B16_0 + B16_BYTES)
#define OFF_B32_0 (OFF_B16_1 + B16_BYTES)
#define OFF_B32_1 (OFF_B32_0 + B32_BYTES)
#define GEMM_SMEM_BYTES (OFF_B32_1 + B32_BYTES)   // 145536

// swizzled byte offset of element (row, k) inside an A buffer
__device__ __forceinline__ uint32_t a_off(int r, int k) {
    return (uint32_t)(r * 128) + (uint32_t)((((k >> 2) & 7) ^ (r & 7)) << 4) +
           (uint32_t)((k & 3) << 2);
}

__device__ __forceinline__ float2 lda2(const char* buf, int r, int k) {
    return *(const float2*)(buf + a_off(r, k));
}

__device__ __forceinline__ void load_chunk_A(char* sA, const float* __restrict__ A,
                                             int k0, int tid) {
#pragma unroll
    for (int i = 0; i < 8; i++) {
        int f = i * 512 + tid;
        int row = f >> 3;
        int c4 = f & 7;
        unsigned dst = (unsigned)__cvta_generic_to_shared(
            sA + row * 128 + ((c4 ^ (row & 7)) << 4));
        const float* g = A + (size_t)row * N_EDGES + k0 + c4 * 4;
        asm volatile("cp.async.cg.shared.global [%0], [%1], 16;" ::"r"(dst), "l"(g));
    }
}

// B gather (threads 256..511): edge pair 2gp,2gp+1, n-range gn0..gn0+3
struct BReg { float4 xs0, xd0, xs1, xd1; };

__device__ __forceinline__ void gb_load(BReg& r, const float* __restrict__ h1,
                                        const void* __restrict__ ei, int flag,
                                        int k0, int gp, int gn0) {
    int e = k0 + 2 * gp;
    int s0, d0, s1, d1;
    load_edge(ei, flag, e, s0, d0);
    load_edge(ei, flag, e + 1, s1, d1);
    r.xs0 = __ldg((const float4*)(h1 + (size_t)s0 * 64 + gn0));
    r.xd0 = __ldg((const float4*)(h1 + (size_t)d0 * 64 + gn0));
    r.xs1 = __ldg((const float4*)(h1 + (size_t)s1 * 64 + gn0));
    r.xd1 = __ldg((const float4*)(h1 + (size_t)d1 * 64 + gn0));
}

// cols < 40 -> fp16 [n][k] tile; cols >= 40 -> fp32 [k][c] tile (float4 stores)
__device__ __forceinline__ void gb_store(unsigned short* sB16, float* sB32,
                                         const BReg& r, int gp, int gn0) {
    float v0[4] = {(r.xs0.x + r.xd0.x) * 0.5f, (r.xs0.y + r.xd0.y) * 0.5f,
                   (r.xs0.z + r.xd0.z) * 0.5f, (r.xs0.w + r.xd0.w) * 0.5f};
    float v1[4] = {(r.xs1.x + r.xd1.x) * 0.5f, (r.xs1.y + r.xd1.y) * 0.5f,
                   (r.xs1.z + r.xd1.z) * 0.5f, (r.xs1.w + r.xd1.w) * 0.5f};
    if (gn0 < 40) {
#pragma unroll
        for (int j = 0; j < 4; j++) {
            unsigned pk = pkhalf2(v0[j], v1[j]);
            *(unsigned*)&sB16[(gn0 + j) * SB_HSTRIDE + 2 * gp] = pk;
        }
    } else {
        int c0 = gn0 - 40;
        *(float4*)&sB32[(2 * gp) * B32_STR + c0] = make_float4(v0[0], v0[1], v0[2], v0[3]);
        *(float4*)&sB32[(2 * gp + 1) * B32_STR + c0] = make_float4(v1[0], v1[1], v1[2], v1[3]);
    }
}

__global__ void __launch_bounds__(512, 1) path_gemm_kernel(
    const float* __restrict__ A, const float* __restrict__ h1,
    const void* __restrict__ ei, const int* __restrict__ flagp,
    float* __restrict__ C) {
    extern __shared__ char smem[];
    char* bufA[2] = {smem, smem + A_BUF_BYTES};
    unsigned short* bufB16[2] = {(unsigned short*)(smem + OFF_B16_0),
                                 (unsigned short*)(smem + OFF_B16_1)};
    float* bufB32[2] = {(float*)(smem + OFF_B32_0), (float*)(smem + OFF_B32_1)};

    int tid = threadIdx.x;
    int lane = tid & 31;
    int warp = tid >> 5;
    int flag = *flagp;

    bool is_mma = (warp < 8);
    int rbase = (is_mma ? warp : (warp - 8)) * 64;

    // gather split: threads 256..511 (the fma warps)
    bool gact = (tid >= 256);
    int gp = tid & 15;
    int gn0 = ((tid >> 4) - 16) * 4;

    const int nch = N_EDGES / 32;  // 12500
    int c0 = (int)(((long long)blockIdx.x * nch) / gridDim.x);
    int c1 = (int)(((long long)(blockIdx.x + 1) * nch) / gridDim.x);

    // mma accumulators: 4 m-tiles x 5 n-tiles (cols 0..39)
    float acc[4][5][4] = {};
    // fma accumulators: 2 rows x 12 f32x2 (cols 40..63), fp32 exact
    unsigned long long acc2[2][12];
#pragma unroll
    for (int rr = 0; rr < 2; rr++)
#pragma unroll
        for (int p = 0; p < 12; p++) acc2[rr][p] = 0ULL;

    // ---- prologue: stage chunk c0 ----
    load_chunk_A(bufA[0], A, c0 * 32, tid);
    asm volatile("cp.async.commit_group;");
    if (gact) {
        BReg r;
        gb_load(r, h1, ei, flag, c0 * 32, gp, gn0);
        gb_store(bufB16[0], bufB32[0], r, gp, gn0);
    }
    asm volatile("cp.async.wait_group 0;");
    __syncthreads();

    int buf = 0;
    for (int c = c0; c < c1; ++c) {
        bool more = (c + 1 < c1);
        BReg br;
        if (more) {
            load_chunk_A(bufA[buf ^ 1], A, (c + 1) * 32, tid);
            asm volatile("cp.async.commit_group;");
            if (gact) gb_load(br, h1, ei, flag, (c + 1) * 32, gp, gn0);
        }

        const char* cA = bufA[buf];
        if (is_mma) {
            // ---- tensor engine: cols 0..39 ----
            const unsigned short* cB = bufB16[buf];
            int rb = rbase + (lane >> 2);
            int nb = lane >> 2;
#pragma unroll
            for (int ks = 0; ks < 2; ks++) {
                int ka = ks * 16 + 2 * (lane & 3);
                unsigned a[4][4];
#pragma unroll
                for (int mt = 0; mt < 4; mt++) {
                    int r = rb + mt * 16;
                    float2 w0 = lda2(cA, r, ka);
                    float2 w1 = lda2(cA, r + 8, ka);
                    float2 w2 = lda2(cA, r, ka + 8);
                    float2 w3 = lda2(cA, r + 8, ka + 8);
                    a[mt][0] = pkhalf2(w0.x, w0.y);
                    a[mt][1] = pkhalf2(w1.x, w1.y);
                    a[mt][2] = pkhalf2(w2.x, w2.y);
                    a[mt][3] = pkhalf2(w3.x, w3.y);
                }
#pragma unroll
                for (int ni = 0; ni < 5; ni++) {
                    int hoff = (ni * 8 + nb) * SB_HSTRIDE + ks * 16 + 2 * (lane & 3);
                    unsigned b0 = *(const unsigned*)&cB[hoff];
                    unsigned b1 = *(const unsigned*)&cB[hoff + 8];
#pragma unroll
                    for (int mt = 0; mt < 4; mt++)
                        mma16h(acc[mt][ni], a[mt][0], a[mt][1], a[mt][2], a[mt][3],
                               b0, b1);
                }
            }
        } else {
            // ---- fma engine: cols 40..63, fp32 via f32x2 ----
            unsigned b32a = (unsigned)__cvta_generic_to_shared(bufB32[buf]);
            int row0 = rbase + lane;
            int row1 = row0 + 32;
#pragma unroll
            for (int g = 0; g < 8; g++) {
                float4 a0 = *(const float4*)(cA + a_off(row0, g * 4));
                float4 a1 = *(const float4*)(cA + a_off(row1, g * 4));
                float av0[4] = {a0.x, a0.y, a0.z, a0.w};
                float av1[4] = {a1.x, a1.y, a1.z, a1.w};
#pragma unroll
                for (int t = 0; t < 4; t++) {
                    int k = g * 4 + t;
                    unsigned base = b32a + (unsigned)(k * B32_STR * 4);
                    unsigned long long bb[12];
#pragma unroll
                    for (int q = 0; q < 6; q++) {
                        asm("ld.shared.v2.b64 {%0, %1}, [%2];"
                            : "=l"(bb[2 * q]), "=l"(bb[2 * q + 1])
                            : "r"(base + q * 16));
                    }
                    unsigned long long ad0, ad1;
                    asm("mov.b64 %0, {%1, %1};" : "=l"(ad0) : "f"(av0[t]));
                    asm("mov.b64 %0, {%1, %1};" : "=l"(ad1) : "f"(av1[t]));
#pragma unroll
                    for (int p = 0; p < 12; p++) {
                        asm("fma.rn.f32x2 %0, %1, %2, %0;"
                            : "+l"(acc2[0][p]) : "l"(ad0), "l"(bb[p]));
                        asm("fma.rn.f32x2 %0, %1, %2, %0;"
                            : "+l"(acc2[1][p]) : "l"(ad1), "l"(bb[p]));
                    }
                }
            }
        }

        if (more) {
            if (gact) gb_store(bufB16[buf ^ 1], bufB32[buf ^ 1], br, gp, gn0);
            asm volatile("cp.async.wait_group 0;");
        }
        __syncthreads();
        buf ^= 1;
    }

    // ---- epilogue ----
    if (is_mma) {
#pragma unroll
        for (int mt = 0; mt < 4; mt++) {
            int row = rbase + mt * 16 + (lane >> 2);
#pragma unroll
            for (int ni = 0; ni < 5; ni++) {
                int col = ni * 8 + 2 * (lane & 3);
                atomicAdd((float2*)&C[row * 64 + col],
                          make_float2(acc[mt][ni][0], acc[mt][ni][1]));
                atomicAdd((float2*)&C[(row + 8) * 64 + col],
                          make_float2(acc[mt][ni][2], acc[mt][ni][3]));
            }
        }
    } else {
#pragma unroll
        for (int rr = 0; rr < 2; rr++) {
            int row = rbase + lane + rr * 32;
#pragma unroll
            for (int q = 0; q < 6; q++) {
                float x0, y0, x1, y1;
                asm("mov.b64 {%0, %1}, %2;" : "=f"(x0), "=f"(y0) : "l"(acc2[rr][2 * q]));
                asm("mov.b64 {%0, %1}, %2;" : "=f"(x1), "=f"(y1) : "l"(acc2[rr][2 * q + 1]));
                atomicAdd((float4*)&C[row * 64 + 40 + q * 4],
                          make_float4(x0, y0, x1, y1));
            }
        }
    }
}

// ---------------- readout ----------------
__global__ void readout_kernel(const float* __restrict__ P,
                               const float* __restrict__ W,
                               const float* __restrict__ b,
                               float* __restrict__ out) {
    int p = blockIdx.x;
    int d = threadIdx.x;
    float s = __ldg(&b[d]);
    const float* pr = P + p * 64;
#pragma unroll 16
    for (int k = 0; k < 64; k++) s += __ldg(&pr[k]) * __ldg(&W[k * 64 + d]);
    out[p * 64 + d] = s;
}

// ---------------- launcher ----------------
extern "C" void kernel_launch(void* const* d_in, const int* in_sizes, int n_in,
                              void* d_out, int out_size) {
    (void)in_sizes; (void)n_in; (void)out_size;
    const float* x   = (const float*)d_in[0];
    const void*  ei  = d_in[1];
    const float* pm  = (const float*)d_in[2];
    const float* Wl0 = (const float*)d_in[3];
    const float* Wr0 = (const float*)d_in[4];
    const float* bl0 = (const float*)d_in[5];
    const float* Wl1 = (const float*)d_in[6];
    const float* Wr1 = (const float*)d_in[7];
    const float* bl1 = (const float*)d_in[8];
    const float* Wro = (const float*)d_in[9];
    const float* bro = (const float*)d_in[10];
    float* out       = (float*)d_out;

    float *deg, *agg0, *agg1, *h0, *h1, *pemb;
    int *flag;
    cudaGetSymbolAddress((void**)&deg,  g_deg);
    cudaGetSymbolAddress((void**)&agg0, g_agg0);
    cudaGetSymbolAddress((void**)&agg1, g_agg1);
    cudaGetSymbolAddress((void**)&h0,   g_h0);
    cudaGetSymbolAddress((void**)&h1,   g_h1);
    cudaGetSymbolAddress((void**)&pemb, g_path);
    cudaGetSymbolAddress((void**)&flag, g_is32);

    cudaFuncSetAttribute(path_gemm_kernel,
                         cudaFuncAttributeMaxDynamicSharedMemorySize, GEMM_SMEM_BYTES);
    cudaFuncSetAttribute(sage_mma_kernel,
                         cudaFuncAttributeMaxDynamicSharedMemorySize, SAGE_SMEM_BYTES);

    init_kernel<<<(N_NODES * DIM + 255) / 256, 256>>>(deg, agg0, agg1, pemb, flag,
                                                      (const int*)ei);
    scatter_kernel<true><<<(N_EDGES * 16 + 255) / 256, 256>>>(x, ei, flag, agg0, deg);
    sage_mma_kernel<<<391, 256, SAGE_SMEM_BYTES>>>(agg0, deg, x, Wl0, Wr0, bl0, h0);
    scatter_kernel<false><<<(N_EDGES * 16 + 255) / 256, 256>>>(h0, ei, flag, agg1, deg);
    sage_mma_kernel<<<391, 256, SAGE_SMEM_BYTES>>>(agg1, deg, h0, Wl1, Wr1, bl1, h1);
    path_gemm_kernel<<<148, 512, GEMM_SMEM_BYTES>>>(pm, h1, ei, flag, pemb);
    readout_kernel<<<N_PATHS, 64>>>(pemb, Wro, bro, out);
}

// round 11
// speedup vs baseline: 1.9635x; 1.9635x over previous
#include <cuda_runtime.h>
#include <cstdint>

#define N_NODES 50000
#define N_EDGES 400000
#define N_PATHS 512
#define DIM 64

// ---------------- device scratch (static: no runtime allocation) ----------------
__device__ float g_deg[N_NODES];
__device__ float g_agg0[N_NODES * DIM];
__device__ float g_agg1[N_NODES * DIM];
__device__ float g_h0[N_NODES * DIM];
__device__ float g_h1[N_NODES * DIM];
__device__ float g_path[N_PATHS * DIM];
__device__ int   g_is32;

// ---------------- common helpers ----------------
__device__ __forceinline__ unsigned f2tf32(float f) {
    unsigned u;
    asm("cvt.rna.tf32.f32 %0, %1;" : "=r"(u) : "f"(f));
    return u;
}

__device__ __forceinline__ void mma8(float* c, const unsigned* a, unsigned b0, unsigned b1) {
    asm volatile(
        "mma.sync.aligned.m16n8k8.row.col.f32.tf32.tf32.f32 "
        "{%0,%1,%2,%3}, {%4,%5,%6,%7}, {%8,%9}, {%0,%1,%2,%3};"
        : "+f"(c[0]), "+f"(c[1]), "+f"(c[2]), "+f"(c[3])
        : "r"(a[0]), "r"(a[1]), "r"(a[2]), "r"(a[3]), "r"(b0), "r"(b1));
}

__device__ __forceinline__ void cp16(float* sdst, const float* gsrc) {
    unsigned s = (unsigned)__cvta_generic_to_shared(sdst);
    asm volatile("cp.async.cg.shared.global [%0], [%1], 16;" ::"r"(s), "l"(gsrc));
}

// on-the-fly edge index fetch (handles int32 or int64 payload)
__device__ __forceinline__ void load_edge(const void* ei, int flag, int e,
                                          int& s, int& d) {
    if (flag) {
        const int* p = (const int*)ei;
        s = __ldg(&p[e]);
        d = __ldg(&p[N_EDGES + e]);
    } else {
        const long long* p = (const long long*)ei;
        s = (int)__ldg(&p[e]);
        d = (int)__ldg(&p[N_EDGES + e]);
    }
}

// ---------------- launch 1: fused init (zero scratch) + dtype probe (block 0) ----------------
__global__ void init_kernel(float* __restrict__ deg, float* __restrict__ agg0,
                            float* __restrict__ agg1, float* __restrict__ pemb,
                            int* __restrict__ flag, const int* __restrict__ ei_w) {
    int i = blockIdx.x * blockDim.x + threadIdx.x;
    if (i < N_NODES) deg[i] = 0.0f;
    if (i < N_NODES * DIM) { agg0[i] = 0.0f; agg1[i] = 0.0f; }
    if (i < N_PATHS * DIM) pemb[i] = 0.0f;
    if (blockIdx.x == 0) {
        int t = threadIdx.x;
        int nz = 0;
#pragma unroll
        for (int k = 0; k < 16; k++) {
            int idx = t * 16 + k;  // 4096 probed entries
            if (ei_w[2 * idx + 1] != 0) nz = 1;
        }
        int any = __syncthreads_or(nz);
        if (t == 0) *flag = any;
    }
}

// ---------------- scatter-sum: agg[dst] += x[src]; optional degree count ----------------
template <bool WITH_DEG>
__global__ void scatter_kernel(const float* __restrict__ x,
                               const void* __restrict__ ei,
                               const int* __restrict__ flagp,
                               float* __restrict__ agg,
                               float* __restrict__ deg) {
    int idx = blockIdx.x * blockDim.x + threadIdx.x;
    if (idx >= N_EDGES * 16) return;
    int e = idx >> 4;
    int j = idx & 15;
    int flag = *flagp;
    int s, d;
    load_edge(ei, flag, e, s, d);
    if (WITH_DEG && j == 0) atomicAdd(&deg[d], 1.0f);
    float4 v = __ldg((const float4*)x + (size_t)s * 16 + j);
    atomicAdd((float4*)agg + (size_t)d * 16 + j, v);
}

// ---------------- SAGE layer via tf32 mma: h = relu([agg/deg, x] @ [Wl;Wr] + bl) ----------------
#define SAGE_AX_STRIDE 132
#define SAGE_W_STRIDE 72
#define SAGE_SMEM_BYTES ((128 * SAGE_AX_STRIDE + 128 * SAGE_W_STRIDE) * 4)

__global__ void __launch_bounds__(256) sage_mma_kernel(
    const float* __restrict__ agg, const float* __restrict__ deg,
    const float* __restrict__ x, const float* __restrict__ Wl,
    const float* __restrict__ Wr, const float* __restrict__ bl,
    float* __restrict__ h) {
    extern __shared__ float sm[];
    float* sAX = sm;
    float* sW  = sm + 128 * SAGE_AX_STRIDE;

    int tid = threadIdx.x;
    int lane = tid & 31;
    int warp = tid >> 5;

    for (int i = tid; i < 1024; i += 256) {
        int k = i >> 4, c4 = i & 15;
        float4 wl = ((const float4*)Wl)[i];
        float4 wr = ((const float4*)Wr)[i];
        *(float4*)&sW[k * SAGE_W_STRIDE + c4 * 4] = wl;
        *(float4*)&sW[(k + 64) * SAGE_W_STRIDE + c4 * 4] = wr;
    }

    int bc = (lane & 3) * 2;
    float bias0[8], bias1[8];
#pragma unroll
    for (int ni = 0; ni < 8; ni++) {
        bias0[ni] = __ldg(&bl[ni * 8 + bc]);
        bias1[ni] = __ldg(&bl[ni * 8 + bc + 1]);
    }

    int ntiles = (N_NODES + 127) / 128;
    for (int t = blockIdx.x; t < ntiles; t += gridDim.x) {
        int base = t * 128;
        __syncthreads();
        for (int i = tid; i < 2048; i += 256) {
            int r = i >> 4, c4 = i & 15;
            int row = base + r;
            float4 va = make_float4(0.f, 0.f, 0.f, 0.f);
            float4 vx = va;
            if (row < N_NODES) {
                va = ((const float4*)agg)[(size_t)row * 16 + c4];
                float iv = 1.0f / fmaxf(deg[row], 1.0f);
                va.x *= iv; va.y *= iv; va.z *= iv; va.w *= iv;
                vx = ((const float4*)x)[(size_t)row * 16 + c4];
            }
            *(float4*)&sAX[r * SAGE_AX_STRIDE + c4 * 4] = va;
            *(float4*)&sAX[r * SAGE_AX_STRIDE + 64 + c4 * 4] = vx;
        }
        __syncthreads();

        float acc[8][4];
#pragma unroll
        for (int ni = 0; ni < 8; ni++) {
            acc[ni][0] = bias0[ni];
            acc[ni][1] = bias1[ni];
            acc[ni][2] = bias0[ni];
            acc[ni][3] = bias1[ni];
        }

        int rb = warp * 16 + (lane >> 2);
        int nb = lane >> 2;
#pragma unroll
        for (int kk = 0; kk < 128; kk += 8) {
            int kA = kk + (lane & 3);
            unsigned a[4];
            a[0] = f2tf32(sAX[rb * SAGE_AX_STRIDE + kA]);
            a[1] = f2tf32(sAX[(rb + 8) * SAGE_AX_STRIDE + kA]);
            a[2] = f2tf32(sAX[rb * SAGE_AX_STRIDE + kA + 4]);
            a[3] = f2tf32(sAX[(rb + 8) * SAGE_AX_STRIDE + kA + 4]);
#pragma unroll
            for (int ni = 0; ni < 8; ni++) {
                unsigned b0 = f2tf32(sW[kA * SAGE_W_STRIDE + ni * 8 + nb]);
                unsigned b1 = f2tf32(sW[(kA + 4) * SAGE_W_STRIDE + ni * 8 + nb]);
                mma8(acc[ni], a, b0, b1);
            }
        }

        int r0 = base + rb;
#pragma unroll
        for (int ni = 0; ni < 8; ni++) {
            int col = ni * 8 + bc;
            if (r0 < N_NODES) {
                float2 o = make_float2(fmaxf(acc[ni][0], 0.f), fmaxf(acc[ni][1], 0.f));
                *(float2*)&h[(size_t)r0 * 64 + col] = o;
            }
            if (r0 + 8 < N_NODES) {
                float2 o = make_float2(fmaxf(acc[ni][2], 0.f), fmaxf(acc[ni][3], 0.f));
                *(float2*)&h[(size_t)(r0 + 8) * 64 + col] = o;
            }
        }
    }
}

// ---------------- big GEMM (R4-best structure, M-split for 2 CTAs/SM) ----------------
// path_emb[512,64] += path_masks[512,K] @ B[K,64], B[k,:] = (h1[src[k]]+h1[dst[k]])*0.5
// grid = 296: (K-slice = bid>>1) x (M-half = bid&1, 256 rows each).
// Two co-resident CTAs per SM hide each other's load/combine/sync tails on the
// shared tensor pipe. tf32 mma.sync m16n8k8; gather via cp.async + smem combine.
#define SA_ROWS 256
#define SA_STRIDE 36
#define SB_STRIDE 72
#define SA_FLOATS (SA_ROWS * SA_STRIDE)              // 9216
#define SB_FLOATS (32 * SB_STRIDE)                   // 2304
#define BUF_FLOATS (SA_FLOATS + 2 * SB_FLOATS)       // 13824
#define GEMM_SMEM_BYTES (2 * BUF_FLOATS * 4)         // 110592 (x2 CTAs = 221184/SM)

__device__ __forceinline__ void load_chunk_A(float* sA, const float* __restrict__ A,
                                             int k0, int tid) {
    // 256 rows x 32 k = 2048 float4, 256 threads -> 8 each
#pragma unroll
    for (int i = 0; i < 8; i++) {
        int f = i * 256 + tid;
        int row = f >> 3;
        int c4 = f & 7;
        cp16(sA + row * SA_STRIDE + c4 * 4,
             A + (size_t)row * N_EDGES + k0 + c4 * 4);
    }
}

// async-gather both endpoint rows of 32 edges into sB1 / sB2 (2 float4/thread each)
__device__ __forceinline__ void gather_chunk_B(float* sB1, float* sB2,
                                               const float* __restrict__ h1,
                                               const void* __restrict__ ei,
                                               int flag, int k0, int tid) {
#pragma unroll
    for (int i = 0; i < 2; i++) {
        int f = i * 256 + tid;
        int e = f >> 4;
        int j = f & 15;
        int s, d;
        load_edge(ei, flag, k0 + e, s, d);
        cp16(sB1 + e * SB_STRIDE + j * 4, h1 + (size_t)s * 64 + j * 4);
        cp16(sB2 + e * SB_STRIDE + j * 4, h1 + (size_t)d * 64 + j * 4);
    }
}

// sB1 = 0.5*(sB1 + sB2): 512 float4, 2 per thread
__device__ __forceinline__ void combine_B(float* sB1, const float* sB2, int tid) {
#pragma unroll
    for (int i = 0; i < 2; i++) {
        int f = i * 256 + tid;
        int row = f >> 4;
        int c4 = f & 15;
        float4 a = *(float4*)&sB1[row * SB_STRIDE + c4 * 4];
        float4 b = *(const float4*)&sB2[row * SB_STRIDE + c4 * 4];
        a.x = (a.x + b.x) * 0.5f;
        a.y = (a.y + b.y) * 0.5f;
        a.z = (a.z + b.z) * 0.5f;
        a.w = (a.w + b.w) * 0.5f;
        *(float4*)&sB1[row * SB_STRIDE + c4 * 4] = a;
    }
}

__global__ void __launch_bounds__(256, 2) path_gemm_kernel(
    const float* __restrict__ A, const float* __restrict__ h1,
    const void* __restrict__ ei, const int* __restrict__ flagp,
    float* __restrict__ C) {
    extern __shared__ float sm[];
    float* bufA[2]  = {sm, sm + BUF_FLOATS};
    float* bufB1[2] = {sm + SA_FLOATS, sm + BUF_FLOATS + SA_FLOATS};
    float* bufB2[2] = {sm + SA_FLOATS + SB_FLOATS,
                       sm + BUF_FLOATS + SA_FLOATS + SB_FLOATS};

    int tid = threadIdx.x;
    int lane = tid & 31;
    int warp = tid >> 5;
    int m0 = warp * 32;                 // 8 warps x 32 rows (local)
    int flag = *flagp;

    int kslice = blockIdx.x >> 1;       // 0..147
    int mbase = (blockIdx.x & 1) * 256; // M half

    const float* Am = A + (size_t)mbase * N_EDGES;

    const int nch = N_EDGES / 32;  // 12500
    int c0 = (int)(((long long)kslice * nch) / 148);
    int c1 = (int)(((long long)(kslice + 1) * nch) / 148);

    float acc[2][8][4] = {};

    // prologue: stage + combine chunk c0
    load_chunk_A(bufA[0], Am, c0 * 32, tid);
    gather_chunk_B(bufB1[0], bufB2[0], h1, ei, flag, c0 * 32, tid);
    asm volatile("cp.async.commit_group;");
    asm volatile("cp.async.wait_group 0;");
    __syncthreads();
    combine_B(bufB1[0], bufB2[0], tid);
    __syncthreads();

    int buf = 0;
    for (int c = c0; c < c1; ++c) {
        float* cA = bufA[buf];
        float* cB = bufB1[buf];
        bool more = (c + 1 < c1);
        if (more) {
            load_chunk_A(bufA[buf ^ 1], Am, (c + 1) * 32, tid);
            gather_chunk_B(bufB1[buf ^ 1], bufB2[buf ^ 1], h1, ei, flag,
                           (c + 1) * 32, tid);
            asm volatile("cp.async.commit_group;");
        }

#pragma unroll
        for (int kk = 0; kk < 32; kk += 8) {
            unsigned a[2][4];
            int rb = m0 + (lane >> 2);
            int kA = kk + (lane & 3);
#pragma unroll
            for (int mi = 0; mi < 2; mi++) {
                int r = rb + mi * 16;
                a[mi][0] = f2tf32(cA[r * SA_STRIDE + kA]);
                a[mi][1] = f2tf32(cA[(r + 8) * SA_STRIDE + kA]);
                a[mi][2] = f2tf32(cA[r * SA_STRIDE + kA + 4]);
                a[mi][3] = f2tf32(cA[(r + 8) * SA_STRIDE + kA + 4]);
            }
            int nb = lane >> 2;
#pragma unroll
            for (int ni = 0; ni < 8; ni++) {
                unsigned b0 = f2tf32(cB[kA * SB_STRIDE + ni * 8 + nb]);
                unsigned b1 = f2tf32(cB[(kA + 4) * SB_STRIDE + ni * 8 + nb]);
                mma8(acc[0][ni], a[0], b0, b1);
                mma8(acc[1][ni], a[1], b0, b1);
            }
        }

        if (more) {
            asm volatile("cp.async.wait_group 0;");
            __syncthreads();
            combine_B(bufB1[buf ^ 1], bufB2[buf ^ 1], tid);
        }
        __syncthreads();
        buf ^= 1;
    }

    // epilogue: accumulate C tile with vector L2 reductions
#pragma unroll
    for (int mi = 0; mi < 2; mi++) {
        int row = mbase + m0 + mi * 16 + (lane >> 2);
#pragma unroll
        for (int ni = 0; ni < 8; ni++) {
            int col = ni * 8 + 2 * (lane & 3);
            atomicAdd((float2*)&C[row * 64 + col],
                      make_float2(acc[mi][ni][0], acc[mi][ni][1]));
            atomicAdd((float2*)&C[(row + 8) * 64 + col],
                      make_float2(acc[mi][ni][2], acc[mi][ni][3]));
        }
    }
}

// ---------------- readout: out = path_emb @ Wro + bro ----------------
__global__ void readout_kernel(const float* __restrict__ P,
                               const float* __restrict__ W,
                               const float* __restrict__ b,
                               float* __restrict__ out) {
    int p = blockIdx.x;
    int d = threadIdx.x;
    float s = __ldg(&b[d]);
    const float* pr = P + p * 64;
#pragma unroll 16
    for (int k = 0; k < 64; k++) s += __ldg(&pr[k]) * __ldg(&W[k * 64 + d]);
    out[p * 64 + d] = s;
}

// ---------------- launcher ----------------
extern "C" void kernel_launch(void* const* d_in, const int* in_sizes, int n_in,
                              void* d_out, int out_size) {
    (void)in_sizes; (void)n_in; (void)out_size;
    const float* x   = (const float*)d_in[0];
    const void*  ei  = d_in[1];
    const float* pm  = (const float*)d_in[2];
    const float* Wl0 = (const float*)d_in[3];
    const float* Wr0 = (const float*)d_in[4];
    const float* bl0 = (const float*)d_in[5];
    const float* Wl1 = (const float*)d_in[6];
    const float* Wr1 = (const float*)d_in[7];
    const float* bl1 = (const float*)d_in[8];
    const float* Wro = (const float*)d_in[9];
    const float* bro = (const float*)d_in[10];
    float* out       = (float*)d_out;

    float *deg, *agg0, *agg1, *h0, *h1, *pemb;
    int *flag;
    cudaGetSymbolAddress((void**)&deg,  g_deg);
    cudaGetSymbolAddress((void**)&agg0, g_agg0);
    cudaGetSymbolAddress((void**)&agg1, g_agg1);
    cudaGetSymbolAddress((void**)&h0,   g_h0);
    cudaGetSymbolAddress((void**)&h1,   g_h1);
    cudaGetSymbolAddress((void**)&pemb, g_path);
    cudaGetSymbolAddress((void**)&flag, g_is32);

    cudaFuncSetAttribute(path_gemm_kernel,
                         cudaFuncAttributeMaxDynamicSharedMemorySize, GEMM_SMEM_BYTES);
    cudaFuncSetAttribute(sage_mma_kernel,
                         cudaFuncAttributeMaxDynamicSharedMemorySize, SAGE_SMEM_BYTES);

    // 1: fused zero/init + dtype probe
    init_kernel<<<(N_NODES * DIM + 255) / 256, 256>>>(deg, agg0, agg1, pemb, flag,
                                                      (const int*)ei);
    // 2: layer-0 scatter (+degree)
    scatter_kernel<true><<<(N_EDGES * 16 + 255) / 256, 256>>>(x, ei, flag, agg0, deg);
    // 3: layer-0 sage
    sage_mma_kernel<<<391, 256, SAGE_SMEM_BYTES>>>(agg0, deg, x, Wl0, Wr0, bl0, h0);
    // 4: layer-1 scatter
    scatter_kernel<false><<<(N_EDGES * 16 + 255) / 256, 256>>>(h0, ei, flag, agg1, deg);
    // 5: layer-1 sage
    sage_mma_kernel<<<391, 256, SAGE_SMEM_BYTES>>>(agg1, deg, h0, Wl1, Wr1, bl1, h1);
    // 6: big split-K GEMM (tf32 mma, 2 CTAs/SM to hide chunk tails)
    path_gemm_kernel<<<296, 256, GEMM_SMEM_BYTES>>>(pm, h1, ei, flag, pemb);
    // 7: readout
    readout_kernel<<<N_PATHS, 64>>>(pemb, Wro, bro, out);
}